// round 6
// baseline (speedup 1.0000x reference)
#include <cuda_runtime.h>
#include <cstdint>

// ---------------------------------------------------------------------------
// HVGGBlock in tangent space; convs via mma.sync tf32 implicit GEMM.
// logmap fused into conv1's tile build; BN+clamp+relu fused into conv2's;
// BN statistics fused into both conv epilogues (no standalone stats pass).
//   logmap0(project(expmap0(u))) == clampnorm(u, R), R = artanh(1-1e-4)
// ---------------------------------------------------------------------------

#define NB   8
#define CH   32
#define HH   256
#define WW   256
#define PLANE (HH*WW)
#define IMG   (CH*PLANE)
#define NPIX  (NB*PLANE)

#define R_CLAMP 4.9517188f
#define MAXN    0.9999f

__device__ __align__(16) float g_bufA[NB*IMG];
__device__ __align__(16) float g_bufB[NB*IMG];
__device__ float g_stats[128];   // [0:32) sum1 [32:64) sq1 [64:96) sum2 [96:128) sq2
__device__ float g_aff[128];
__device__ __align__(16) uint32_t g_wpack[2*36*4*32*2];

__device__ __forceinline__ uint32_t f2tf32(float f) {
    uint32_t r; asm("cvt.rna.tf32.f32 %0, %1;" : "=r"(r) : "f"(f)); return r;
}

// ---- weight pack: [layer][s][Nt][lane] -> {b0,b1}; 4608 entries/layer -------
__global__ void __launch_bounds__(256) pack_w_kernel(const float* __restrict__ w1,
                                                     const float* __restrict__ w2) {
    int id = blockIdx.x * 256 + threadIdx.x;
    if (id >= 9216) return;
    int lay = id / 4608;
    int r   = id - lay * 4608;
    int l   = r & 31;
    int Nt  = (r >> 5) & 3;
    int s   = r >> 7;
    int tg = l & 3, gd = l >> 2;
    int co = Nt * 8 + gd;
    int t  = s >> 2;
    int c0 = (s & 3) * 8 + tg;
    const float* w = lay ? w2 : w1;
    uint32_t b0 = f2tf32(w[(co * CH + c0) * 9 + t]);
    uint32_t b1 = f2tf32(w[(co * CH + c0 + 4) * 9 + t]);
    uint2* dst = (uint2*)(g_wpack + lay * 9216);
    dst[(s * 4 + Nt) * 32 + l] = make_uint2(b0, b1);
}

// ---- fused conv kernel -------------------------------------------------------
#define PSTRIDE 620
#define SMEM_BYTES (16*PSTRIDE*8)     // 79360 dynamic

// MODE 0: src=x, logmap, dst=g_bufB, layer 0, stats -> g_stats[0..63]
// MODE 1: src=g_bufB, BN(aff0)+clamp+relu, dst=g_bufA, layer 1, stats -> [64..127]
template<int MODE>
__global__ void __launch_bounds__(256, 2)
conv_fused_kernel(const float* __restrict__ ext, const float* __restrict__ bias) {
    extern __shared__ __align__(16) uint2 s_in[];   // [16][PSTRIDE]
    __shared__ float s_stats[64];                   // [0:32) sum [32:64) sumsq

    const int tid  = threadIdx.x;
    const int wid  = tid >> 5;
    const int lane = tid & 31;
    const int gid  = lane >> 2;
    const int tig  = lane & 3;
    const int n    = blockIdx.z;
    const int gy0  = blockIdx.y * 16;
    const int gx0  = blockIdx.x * 32;

    if (tid < 64) s_stats[tid] = 0.f;

    const float* src = (MODE == 0) ? (ext + n * IMG) : (g_bufB + n * IMG);

    // ---- build: per-pixel transform + pair-layout tf32 store ----------------
    for (int p = tid; p < 612; p += 256) {
        int r = p / 34, c = p - r * 34;
        int gy = gy0 + r - 1, gx = gx0 + c - 1;
        bool inb = ((unsigned)gy < 256u) && ((unsigned)gx < 256u);
        float v[CH];
        if (inb) {
            const float* sp = src + gy * WW + gx;
            float ss = 0.f;
#pragma unroll
            for (int ci = 0; ci < CH; ci++) {
                float u = sp[ci * PLANE];
                if (MODE == 1) u = u * g_aff[ci] + g_aff[32 + ci];
                v[ci] = u; ss += u * u;
            }
            float f;
            if (MODE == 0) {
                float nrm = sqrtf(ss);
                float nn  = fmaxf(nrm, 1e-5f);
                float t   = fminf(nn, 1.f - 1e-5f);
                f = 0.5f * (log1pf(t) - log1pf(-t)) / nn;          // logmap0
            } else {
                float nrm = sqrtf(ss);
                f = (nrm > R_CLAMP) ? (R_CLAMP / nrm) : 1.0f;      // clampnorm
            }
#pragma unroll
            for (int ci = 0; ci < CH; ci++) {
                float u = v[ci] * f;
                if (MODE == 1) u = fmaxf(u, 0.f);                  // relu
                v[ci] = u;
            }
        } else {
#pragma unroll
            for (int ci = 0; ci < CH; ci++) v[ci] = 0.f;
        }
#pragma unroll
        for (int g = 0; g < 4; g++)
#pragma unroll
            for (int q4 = 0; q4 < 4; q4++)
                s_in[(g * 4 + q4) * PSTRIDE + p] =
                    make_uint2(f2tf32(v[g * 8 + q4]), f2tf32(v[g * 8 + q4 + 4]));
    }
    __syncthreads();

    // ---- implicit GEMM: warp owns 2 pixel rows, 4 M-tiles, N=32 -------------
    const uint2* wp = (const uint2*)(g_wpack + MODE * 9216);
    float acc[4][4][4];
#pragma unroll
    for (int i = 0; i < 4; i++)
#pragma unroll
        for (int Nt = 0; Nt < 4; Nt++)
#pragma unroll
            for (int j = 0; j < 4; j++) acc[i][Nt][j] = 0.f;

    const int warp_row = wid * 2;

#pragma unroll 4
    for (int s = 0; s < 36; s++) {
        int t  = s >> 2;
        int ky = (t >= 6) ? 2 : (t >= 3 ? 1 : 0);
        int kx = t - ky * 3;
        int q  = (s & 3) * 4 + tig;

        uint2 b[4];
#pragma unroll
        for (int Nt = 0; Nt < 4; Nt++) b[Nt] = wp[(s * 4 + Nt) * 32 + lane];

        int pixbase = q * PSTRIDE + (warp_row + ky) * 34 + kx + gid;
#pragma unroll
        for (int i = 0; i < 4; i++) {
            int px = pixbase + (i >> 1) * 34 + (i & 1) * 16;
            uint2 A0 = s_in[px];
            uint2 A1 = s_in[px + 8];
#pragma unroll
            for (int Nt = 0; Nt < 4; Nt++) {
                asm volatile(
                    "mma.sync.aligned.m16n8k8.row.col.f32.tf32.tf32.f32 "
                    "{%0,%1,%2,%3}, {%4,%5,%6,%7}, {%8,%9}, {%0,%1,%2,%3};"
                    : "+f"(acc[i][Nt][0]), "+f"(acc[i][Nt][1]),
                      "+f"(acc[i][Nt][2]), "+f"(acc[i][Nt][3])
                    : "r"(A0.x), "r"(A1.x), "r"(A0.y), "r"(A1.y),
                      "r"(b[Nt].x), "r"(b[Nt].y));
            }
        }
    }

    // ---- epilogue: bias + per-pixel clampnorm + store + fused BN stats -------
    float2 bs[4];
#pragma unroll
    for (int Nt = 0; Nt < 4; Nt++)
        bs[Nt] = *(const float2*)(bias + Nt * 8 + 2 * tig);

    float sAcc[8], qAcc[8];
#pragma unroll
    for (int j = 0; j < 8; j++) { sAcc[j] = 0.f; qAcc[j] = 0.f; }

    float* outN = (MODE == 0 ? g_bufB : g_bufA) + n * IMG;
#pragma unroll
    for (int i = 0; i < 4; i++) {
        int yl = warp_row + (i >> 1);
        int xl = (i & 1) * 16 + gid;
        float vA[8], vB[8];
        float ssA = 0.f, ssB = 0.f;
#pragma unroll
        for (int Nt = 0; Nt < 4; Nt++) {
            float a0 = acc[i][Nt][0] + bs[Nt].x;
            float a1 = acc[i][Nt][1] + bs[Nt].y;
            float b0 = acc[i][Nt][2] + bs[Nt].x;
            float b1 = acc[i][Nt][3] + bs[Nt].y;
            vA[2 * Nt] = a0; vA[2 * Nt + 1] = a1;
            vB[2 * Nt] = b0; vB[2 * Nt + 1] = b1;
            ssA += a0 * a0 + a1 * a1;
            ssB += b0 * b0 + b1 * b1;
        }
        ssA += __shfl_xor_sync(0xffffffffu, ssA, 1);
        ssA += __shfl_xor_sync(0xffffffffu, ssA, 2);
        ssB += __shfl_xor_sync(0xffffffffu, ssB, 1);
        ssB += __shfl_xor_sync(0xffffffffu, ssB, 2);
        float nA = sqrtf(ssA), nB = sqrtf(ssB);
        float fA = (nA > R_CLAMP) ? (R_CLAMP / nA) : 1.0f;
        float fB = (nB > R_CLAMP) ? (R_CLAMP / nB) : 1.0f;
        float* opA = outN + (gy0 + yl) * WW + gx0 + xl;
        float* opB = opA + 8;
#pragma unroll
        for (int Nt = 0; Nt < 4; Nt++) {
            int co = Nt * 8 + 2 * tig;
            float oA0 = vA[2 * Nt] * fA, oA1 = vA[2 * Nt + 1] * fA;
            float oB0 = vB[2 * Nt] * fB, oB1 = vB[2 * Nt + 1] * fB;
            opA[co * PLANE]       = oA0;
            opA[(co + 1) * PLANE] = oA1;
            opB[co * PLANE]       = oB0;
            opB[(co + 1) * PLANE] = oB1;
            sAcc[2 * Nt]     += oA0 + oB0;
            sAcc[2 * Nt + 1] += oA1 + oB1;
            qAcc[2 * Nt]     += oA0 * oA0 + oB0 * oB0;
            qAcc[2 * Nt + 1] += oA1 * oA1 + oB1 * oB1;
        }
    }

    // reduce over the 8 lanes sharing this channel set (same tig, gid 0..7)
#pragma unroll
    for (int j = 0; j < 8; j++) {
#pragma unroll
        for (int o = 4; o <= 16; o <<= 1) {
            sAcc[j] += __shfl_xor_sync(0xffffffffu, sAcc[j], o);
            qAcc[j] += __shfl_xor_sync(0xffffffffu, qAcc[j], o);
        }
    }
    if (gid == 0) {
#pragma unroll
        for (int j = 0; j < 8; j++) {
            int co = (j >> 1) * 8 + 2 * tig + (j & 1);
            atomicAdd(&s_stats[co], sAcc[j]);
            atomicAdd(&s_stats[32 + co], qAcc[j]);
        }
    }
    __syncthreads();
    if (tid < 64) atomicAdd(&g_stats[MODE * 64 + tid], s_stats[tid]);
}

__global__ void zero_stats_kernel() {
    int t = threadIdx.x;
    if (t < 128) g_stats[t] = 0.f;
}

__global__ void finalize_kernel(int statOff, const float* __restrict__ g,
                                const float* __restrict__ beta, int affOff) {
    int c = threadIdx.x;
    if (c >= 32) return;
    const float inv = 1.0f / (float)NPIX;
    float m   = g_stats[statOff + c] * inv;
    float var = fmaxf(g_stats[statOff + 32 + c] * inv - m * m, 0.f);
    float is  = rsqrtf(var + 1e-5f);
    float sc  = g[c] * is;
    g_aff[affOff + c]      = sc;
    g_aff[affOff + 32 + c] = beta[c] - m * sc;
}

// ---- bn + clampnorm + relu + expmap0 + project : bufA -> out -----------------
__global__ void __launch_bounds__(256) final_kernel(int affOff, float* __restrict__ out) {
    int p = blockIdx.x * 256 + threadIdx.x;
    int n = p >> 16, hw = p & 65535;
    const float* ip = g_bufA + n * IMG + hw;
    float u[CH]; float ss = 0.f;
#pragma unroll
    for (int c = 0; c < CH; c++) {
        float v = ip[c << 16];
        u[c] = v * g_aff[affOff + c] + g_aff[affOff + 32 + c];
        ss += u[c] * u[c];
    }
    float nrm = sqrtf(ss);
    float f1 = (nrm > R_CLAMP) ? (R_CLAMP / nrm) : 1.0f;
    float ss2 = 0.f;
#pragma unroll
    for (int c = 0; c < CH; c++) { u[c] = fmaxf(u[c] * f1, 0.f); ss2 += u[c] * u[c]; }
    float nrm2 = sqrtf(ss2);
    float nn  = fmaxf(nrm2, 1e-5f);
    float fac = tanhf(nn) / nn;
    float yn  = fac * nrm2;
    float pm  = fmaxf(yn, 1e-5f);
    float g2  = (pm > MAXN) ? (MAXN / pm) : 1.0f;
    float wsc = fac * g2;
    float* op = out + n * IMG + hw;
#pragma unroll
    for (int c = 0; c < CH; c++) op[c << 16] = u[c] * wsc;
}

// ---------------------------------------------------------------------------
extern "C" void kernel_launch(void* const* d_in, const int* in_sizes, int n_in,
                              void* d_out, int out_size) {
    const float* x   = (const float*)d_in[0];
    const float* w1  = (const float*)d_in[1];
    const float* b1  = (const float*)d_in[2];
    const float* g1  = (const float*)d_in[3];
    const float* be1 = (const float*)d_in[4];
    const float* w2  = (const float*)d_in[5];
    const float* b2  = (const float*)d_in[6];
    const float* g2  = (const float*)d_in[7];
    const float* be2 = (const float*)d_in[8];
    float* out = (float*)d_out;

    cudaFuncSetAttribute(conv_fused_kernel<0>,
                         cudaFuncAttributeMaxDynamicSharedMemorySize, SMEM_BYTES);
    cudaFuncSetAttribute(conv_fused_kernel<1>,
                         cudaFuncAttributeMaxDynamicSharedMemorySize, SMEM_BYTES);

    dim3 cgrid(WW / 32, HH / 16, NB);   // 8 x 16 x 8 = 1024 CTAs

    zero_stats_kernel<<<1, 128>>>();
    pack_w_kernel<<<36, 256>>>(w1, w2);

    conv_fused_kernel<0><<<cgrid, 256, SMEM_BYTES>>>(x, b1);       // x -> bufB (+stats1)
    finalize_kernel<<<1, 32>>>(0, g1, be1, 0);

    conv_fused_kernel<1><<<cgrid, 256, SMEM_BYTES>>>(nullptr, b2); // bufB -> bufA (+stats2)
    finalize_kernel<<<1, 32>>>(64, g2, be2, 64);
    final_kernel<<<NPIX / 256, 256>>>(64, out);
}

// round 7
// speedup vs baseline: 1.0184x; 1.0184x over previous
#include <cuda_runtime.h>
#include <cuda_fp16.h>
#include <cstdint>

// ---------------------------------------------------------------------------
// HVGGBlock in tangent space; convs via mma.sync tf32 implicit GEMM.
// fp16 intermediates (same 10-bit mantissa as tf32 MMA inputs, |v|<=R_CLAMP).
// logmap fused into conv1 build; BN+clamp+relu fused into conv2 build;
// BN affine computed inline from raw stats (no finalize kernels).
//   logmap0(project(expmap0(u))) == clampnorm(u, R), R = artanh(1-1e-4)
// ---------------------------------------------------------------------------

#define NB   8
#define CH   32
#define HH   256
#define WW   256
#define PLANE (HH*WW)
#define IMG   (CH*PLANE)
#define NPIX  (NB*PLANE)

#define R_CLAMP 4.9517188f
#define MAXN    0.9999f

__device__ __align__(16) __half g_bufB[NB*IMG];   // conv1 output
__device__ __align__(16) __half g_bufA[NB*IMG];   // conv2 output
__device__ float g_stats[128];   // [0:32) sum1 [32:64) sq1 [64:96) sum2 [96:128) sq2
__device__ __align__(16) uint32_t g_wpack[2*36*4*32*2];

__device__ __forceinline__ uint32_t f2tf32(float f) {
    uint32_t r; asm("cvt.rna.tf32.f32 %0, %1;" : "=r"(r) : "f"(f)); return r;
}

// ---- weight pack: [layer][s][Nt][lane] -> {b0,b1}; 4608 entries/layer -------
__global__ void __launch_bounds__(256) pack_w_kernel(const float* __restrict__ w1,
                                                     const float* __restrict__ w2) {
    int id = blockIdx.x * 256 + threadIdx.x;
    if (id >= 9216) return;
    int lay = id / 4608;
    int r   = id - lay * 4608;
    int l   = r & 31;
    int Nt  = (r >> 5) & 3;
    int s   = r >> 7;
    int tg = l & 3, gd = l >> 2;
    int co = Nt * 8 + gd;
    int t  = s >> 2;
    int c0 = (s & 3) * 8 + tg;
    const float* w = lay ? w2 : w1;
    uint32_t b0 = f2tf32(w[(co * CH + c0) * 9 + t]);
    uint32_t b1 = f2tf32(w[(co * CH + c0 + 4) * 9 + t]);
    uint2* dst = (uint2*)(g_wpack + lay * 9216);
    dst[(s * 4 + Nt) * 32 + l] = make_uint2(b0, b1);
}

__global__ void zero_stats_kernel() {
    int t = threadIdx.x;
    if (t < 128) g_stats[t] = 0.f;
}

// ---- fused conv kernel -------------------------------------------------------
#define PSTRIDE 620
#define SMEM_BYTES (16*PSTRIDE*8)     // 79360 dynamic

// MODE 0: src = x (fp32), logmap, dst = g_bufB (fp16)
// MODE 1: src = g_bufB (fp16), BN(stats[0:64],g,beta)+clamp+relu, dst = g_bufA
template<int MODE>
__global__ void __launch_bounds__(256, 2)
conv_fused_kernel(const float* __restrict__ ext, const float* __restrict__ bias,
                  const float* __restrict__ gamma, const float* __restrict__ beta) {
    extern __shared__ __align__(16) uint2 s_in[];   // [16][PSTRIDE]
    __shared__ float s_aff[64];

    const int tid  = threadIdx.x;
    const int wid  = tid >> 5;
    const int lane = tid & 31;
    const int gid  = lane >> 2;
    const int tig  = lane & 3;
    const int n    = blockIdx.z;
    const int gy0  = blockIdx.y * 16;
    const int gx0  = blockIdx.x * 32;

    if (MODE == 1) {
        if (tid < 32) {
            const float inv = 1.0f / (float)NPIX;
            float m   = g_stats[tid] * inv;
            float var = fmaxf(g_stats[32 + tid] * inv - m * m, 0.f);
            float is  = rsqrtf(var + 1e-5f);
            float sc  = gamma[tid] * is;
            s_aff[tid]      = sc;
            s_aff[32 + tid] = beta[tid] - m * sc;
        }
        __syncthreads();
    }

    // ---- build: per-pixel transform + pair-layout tf32 store ----------------
    for (int p = tid; p < 612; p += 256) {
        int r = p / 34, c = p - r * 34;
        int gy = gy0 + r - 1, gx = gx0 + c - 1;
        bool inb = ((unsigned)gy < 256u) && ((unsigned)gx < 256u);
        float v[CH];
        if (inb) {
            float ss = 0.f;
            if (MODE == 0) {
                const float* sp = ext + n * IMG + gy * WW + gx;
#pragma unroll
                for (int ci = 0; ci < CH; ci++) {
                    float u = sp[ci * PLANE];
                    v[ci] = u; ss += u * u;
                }
                float nrm = sqrtf(ss);
                float nn  = fmaxf(nrm, 1e-5f);
                float t   = fminf(nn, 1.f - 1e-5f);
                float f   = 0.5f * (log1pf(t) - log1pf(-t)) / nn;   // logmap0
#pragma unroll
                for (int ci = 0; ci < CH; ci++) v[ci] *= f;
            } else {
                const __half* sp = g_bufB + n * IMG + gy * WW + gx;
#pragma unroll
                for (int ci = 0; ci < CH; ci++) {
                    float u = __half2float(sp[ci * PLANE]);
                    u = u * s_aff[ci] + s_aff[32 + ci];
                    v[ci] = u; ss += u * u;
                }
                float nrm = sqrtf(ss);
                float f   = (nrm > R_CLAMP) ? (R_CLAMP / nrm) : 1.0f;
#pragma unroll
                for (int ci = 0; ci < CH; ci++) v[ci] = fmaxf(v[ci] * f, 0.f);
            }
        } else {
#pragma unroll
            for (int ci = 0; ci < CH; ci++) v[ci] = 0.f;
        }
#pragma unroll
        for (int g = 0; g < 4; g++)
#pragma unroll
            for (int q4 = 0; q4 < 4; q4++)
                s_in[(g * 4 + q4) * PSTRIDE + p] =
                    make_uint2(f2tf32(v[g * 8 + q4]), f2tf32(v[g * 8 + q4 + 4]));
    }
    __syncthreads();

    // ---- implicit GEMM: warp owns 2 pixel rows, 4 M-tiles, N=32 -------------
    const uint2* wp = (const uint2*)(g_wpack + MODE * 9216);
    float acc[4][4][4];
#pragma unroll
    for (int i = 0; i < 4; i++)
#pragma unroll
        for (int Nt = 0; Nt < 4; Nt++)
#pragma unroll
            for (int j = 0; j < 4; j++) acc[i][Nt][j] = 0.f;

    const int warp_row = wid * 2;

#pragma unroll 4
    for (int s = 0; s < 36; s++) {
        int t  = s >> 2;
        int ky = (t >= 6) ? 2 : (t >= 3 ? 1 : 0);
        int kx = t - ky * 3;
        int q  = (s & 3) * 4 + tig;

        uint2 b[4];
#pragma unroll
        for (int Nt = 0; Nt < 4; Nt++) b[Nt] = wp[(s * 4 + Nt) * 32 + lane];

        int pixbase = q * PSTRIDE + (warp_row + ky) * 34 + kx + gid;
#pragma unroll
        for (int i = 0; i < 4; i++) {
            int px = pixbase + (i >> 1) * 34 + (i & 1) * 16;
            uint2 A0 = s_in[px];
            uint2 A1 = s_in[px + 8];
#pragma unroll
            for (int Nt = 0; Nt < 4; Nt++) {
                asm volatile(
                    "mma.sync.aligned.m16n8k8.row.col.f32.tf32.tf32.f32 "
                    "{%0,%1,%2,%3}, {%4,%5,%6,%7}, {%8,%9}, {%0,%1,%2,%3};"
                    : "+f"(acc[i][Nt][0]), "+f"(acc[i][Nt][1]),
                      "+f"(acc[i][Nt][2]), "+f"(acc[i][Nt][3])
                    : "r"(A0.x), "r"(A1.x), "r"(A0.y), "r"(A1.y),
                      "r"(b[Nt].x), "r"(b[Nt].y));
            }
        }
    }

    // ---- epilogue: bias + per-pixel clampnorm + fp16 store -------------------
    float2 bs[4];
#pragma unroll
    for (int Nt = 0; Nt < 4; Nt++)
        bs[Nt] = *(const float2*)(bias + Nt * 8 + 2 * tig);

    __half* outN = (MODE == 0 ? g_bufB : g_bufA) + n * IMG;
#pragma unroll
    for (int i = 0; i < 4; i++) {
        int yl = warp_row + (i >> 1);
        int xl = (i & 1) * 16 + gid;
        float vA[8], vB[8];
        float ssA = 0.f, ssB = 0.f;
#pragma unroll
        for (int Nt = 0; Nt < 4; Nt++) {
            float a0 = acc[i][Nt][0] + bs[Nt].x;
            float a1 = acc[i][Nt][1] + bs[Nt].y;
            float b0 = acc[i][Nt][2] + bs[Nt].x;
            float b1 = acc[i][Nt][3] + bs[Nt].y;
            vA[2 * Nt] = a0; vA[2 * Nt + 1] = a1;
            vB[2 * Nt] = b0; vB[2 * Nt + 1] = b1;
            ssA += a0 * a0 + a1 * a1;
            ssB += b0 * b0 + b1 * b1;
        }
        ssA += __shfl_xor_sync(0xffffffffu, ssA, 1);
        ssA += __shfl_xor_sync(0xffffffffu, ssA, 2);
        ssB += __shfl_xor_sync(0xffffffffu, ssB, 1);
        ssB += __shfl_xor_sync(0xffffffffu, ssB, 2);
        float nA = sqrtf(ssA), nB = sqrtf(ssB);
        float fA = (nA > R_CLAMP) ? (R_CLAMP / nA) : 1.0f;
        float fB = (nB > R_CLAMP) ? (R_CLAMP / nB) : 1.0f;
        __half* opA = outN + (gy0 + yl) * WW + gx0 + xl;
        __half* opB = opA + 8;
#pragma unroll
        for (int Nt = 0; Nt < 4; Nt++) {
            int co = Nt * 8 + 2 * tig;
            opA[co * PLANE]       = __float2half_rn(vA[2 * Nt] * fA);
            opA[(co + 1) * PLANE] = __float2half_rn(vA[2 * Nt + 1] * fA);
            opB[co * PLANE]       = __float2half_rn(vB[2 * Nt] * fB);
            opB[(co + 1) * PLANE] = __float2half_rn(vB[2 * Nt + 1] * fB);
        }
    }
}

// ---- per-channel sum/sumsq over fp16 buffer (which: 0 = bufB, 1 = bufA) ------
__global__ void __launch_bounds__(256) stats_kernel(int statOff, int which) {
    const __half* buf = which ? g_bufA : g_bufB;
    int c = blockIdx.y;
    int chunk = blockIdx.x;
    int n = chunk >> 1;
    int off = (chunk & 1) * 32768;
    const uint4* p = reinterpret_cast<const uint4*>(buf + n * IMG + c * PLANE + off);
    float s = 0.f, s2 = 0.f;
    for (int i = threadIdx.x; i < 4096; i += 256) {
        uint4 v = p[i];
        const uint32_t ws[4] = {v.x, v.y, v.z, v.w};
#pragma unroll
        for (int j = 0; j < 4; j++) {
            __half2 h = *reinterpret_cast<const __half2*>(&ws[j]);
            float2 f = __half22float2(h);
            s  += f.x + f.y;
            s2 += f.x * f.x + f.y * f.y;
        }
    }
#pragma unroll
    for (int o = 16; o; o >>= 1) {
        s  += __shfl_xor_sync(0xffffffffu, s, o);
        s2 += __shfl_xor_sync(0xffffffffu, s2, o);
    }
    __shared__ float red[16];
    int warp = threadIdx.x >> 5, lane = threadIdx.x & 31;
    if (lane == 0) { red[warp] = s; red[8 + warp] = s2; }
    __syncthreads();
    if (threadIdx.x == 0) {
        float a = 0.f, b = 0.f;
#pragma unroll
        for (int ww = 0; ww < 8; ww++) { a += red[ww]; b += red[8 + ww]; }
        atomicAdd(&g_stats[statOff + c], a);
        atomicAdd(&g_stats[statOff + 32 + c], b);
    }
}

// ---- bn2 + clampnorm + relu + expmap0 + project : bufA (fp16) -> out (fp32) --
__global__ void __launch_bounds__(256) final_kernel(const float* __restrict__ gamma,
                                                    const float* __restrict__ beta,
                                                    float* __restrict__ out) {
    __shared__ float s_aff[64];
    if (threadIdx.x < 32) {
        int c = threadIdx.x;
        const float inv = 1.0f / (float)NPIX;
        float m   = g_stats[64 + c] * inv;
        float var = fmaxf(g_stats[96 + c] * inv - m * m, 0.f);
        float is  = rsqrtf(var + 1e-5f);
        float sc  = gamma[c] * is;
        s_aff[c]      = sc;
        s_aff[32 + c] = beta[c] - m * sc;
    }
    __syncthreads();

    int p = blockIdx.x * 256 + threadIdx.x;
    int n = p >> 16, hw = p & 65535;
    const __half* ip = g_bufA + n * IMG + hw;
    float u[CH]; float ss = 0.f;
#pragma unroll
    for (int c = 0; c < CH; c++) {
        float v = __half2float(ip[c << 16]);
        u[c] = v * s_aff[c] + s_aff[32 + c];
        ss += u[c] * u[c];
    }
    float nrm = sqrtf(ss);
    float f1 = (nrm > R_CLAMP) ? (R_CLAMP / nrm) : 1.0f;
    float ss2 = 0.f;
#pragma unroll
    for (int c = 0; c < CH; c++) { u[c] = fmaxf(u[c] * f1, 0.f); ss2 += u[c] * u[c]; }
    float nrm2 = sqrtf(ss2);
    float nn  = fmaxf(nrm2, 1e-5f);
    float fac = tanhf(nn) / nn;
    float yn  = fac * nrm2;
    float pm  = fmaxf(yn, 1e-5f);
    float g2  = (pm > MAXN) ? (MAXN / pm) : 1.0f;
    float wsc = fac * g2;
    float* op = out + n * IMG + hw;
#pragma unroll
    for (int c = 0; c < CH; c++) op[c << 16] = u[c] * wsc;
}

// ---------------------------------------------------------------------------
extern "C" void kernel_launch(void* const* d_in, const int* in_sizes, int n_in,
                              void* d_out, int out_size) {
    const float* x   = (const float*)d_in[0];
    const float* w1  = (const float*)d_in[1];
    const float* b1  = (const float*)d_in[2];
    const float* g1  = (const float*)d_in[3];
    const float* be1 = (const float*)d_in[4];
    const float* w2  = (const float*)d_in[5];
    const float* b2  = (const float*)d_in[6];
    const float* g2  = (const float*)d_in[7];
    const float* be2 = (const float*)d_in[8];
    float* out = (float*)d_out;

    cudaFuncSetAttribute(conv_fused_kernel<0>,
                         cudaFuncAttributeMaxDynamicSharedMemorySize, SMEM_BYTES);
    cudaFuncSetAttribute(conv_fused_kernel<1>,
                         cudaFuncAttributeMaxDynamicSharedMemorySize, SMEM_BYTES);

    dim3 cgrid(WW / 32, HH / 16, NB);   // 8 x 16 x 8 = 1024 CTAs

    zero_stats_kernel<<<1, 128>>>();
    pack_w_kernel<<<36, 256>>>(w1, w2);

    conv_fused_kernel<0><<<cgrid, 256, SMEM_BYTES>>>(x, b1, nullptr, nullptr);
    stats_kernel<<<dim3(16, 32), 256>>>(0, 0);

    conv_fused_kernel<1><<<cgrid, 256, SMEM_BYTES>>>(nullptr, b2, g1, be1);
    stats_kernel<<<dim3(16, 32), 256>>>(64, 1);

    final_kernel<<<NPIX / 256, 256>>>(g2, be2, out);
}